// round 11
// baseline (speedup 1.0000x reference)
#include <cuda_runtime.h>
#include <cuda_fp16.h>
#include <cstdint>

#define B_ 64
#define F_ 4096
#define E_ 256
#define H_ 512
#define U_ 512

// ---------------- scratch (__device__ globals: allocation-free rule) -------
__device__ float  g_bias[B_ * U_];     // W1_b[u] + W2_b[u] + hidden@W2
__device__ float  g_scores[B_ * F_];   // pre-softmax scores (V_b dropped: softmax-invariant)
__device__ __half g_W1Th[U_ * E_];     // W1 transposed (u-major, e contiguous) as fp16

__device__ __forceinline__ uint32_t smem_u32(const void* p) {
    uint32_t a;
    asm("{ .reg .u64 t; cvta.to.shared.u64 t, %1; cvt.u32.u64 %0, t; }" : "=r"(a) : "l"(p));
    return a;
}
__device__ __forceinline__ __half2 tanh_h2(__half2 x) {
    uint32_t y;
    asm("tanh.approx.f16x2 %0, %1;" : "=r"(y) : "r"(*(uint32_t*)&x));
    return *(__half2*)&y;
}

#define LDM_X4(r0, r1, r2, r3, addr) \
    asm volatile("ldmatrix.sync.aligned.m8n8.x4.shared.b16 {%0,%1,%2,%3}, [%4];" \
        : "=r"(r0), "=r"(r1), "=r"(r2), "=r"(r3) : "r"(addr))

#define CP_ASYNC_16(dst, src) \
    asm volatile("cp.async.cg.shared.global [%0], [%1], 16;" :: "r"(dst), "l"(src))
#define CP_COMMIT() asm volatile("cp.async.commit_group;" ::: "memory")
#define CP_WAIT(n)  asm volatile("cp.async.wait_group %0;" :: "n"(n) : "memory")

// fp16-accumulate MMA: D,C = 2 regs (4 halves)
__device__ __forceinline__ void mma_f16acc(uint32_t* c, const uint32_t* a,
                                           uint32_t b0, uint32_t b1) {
    asm volatile(
        "mma.sync.aligned.m16n8k16.row.col.f16.f16.f16.f16 "
        "{%0,%1}, {%2,%3,%4,%5}, {%6,%7}, {%0,%1};"
        : "+r"(c[0]), "+r"(c[1])
        : "r"(a[0]), "r"(a[1]), "r"(a[2]), "r"(a[3]), "r"(b0), "r"(b1));
}

// ---------------- smem layout for K2 (byte offsets) ------------------------
// CTA tile: 128 rows (A resident) x 512 u (16 k32-slices); 2 CTAs/SM.
#define LDA 264                 // halves per A row (256+8 pad) -> 528B, conflict-free
#define LDB_BYTES 80            // B row: 32 halves (64B) + 16B pad -> conflict-free ldsm
#define BSTG 20480              // 256 rows * 80B per B stage
#define OFF_AS   0              // 128 * 528 = 67584
#define OFF_BS   67584          // 2 stages * 20480 = 40960 -> 108544
#define OFF_BIAS 108544         // 256 half2 (both U-halves) -> 109568
#define OFF_VW   109568         // 256 half2 -> 110592
#define OFF_SRED 110592         // 128 floats -> 111104
#define SMEM_K2  111104         // x2 CTAs = 222208 B <= 228KB budget

// ---------------------------------------------------------------------------
// K1: merged prep — blocks [0,64): bias; [64,192): W1 transpose; [192,224): zero ctx
// ---------------------------------------------------------------------------
__global__ __launch_bounds__(512) void prep_kernel(
    const float* __restrict__ hidden, const float* __restrict__ W2w,
    const float* __restrict__ W2b, const float* __restrict__ W1b,
    const float* __restrict__ W1w, float* __restrict__ ctx)
{
    const int bid = blockIdx.x;
    const int tid = threadIdx.x;
    if (bid < 64) {
        __shared__ float hs[H_];
        hs[tid] = hidden[bid * H_ + tid];
        __syncthreads();
        float s = W2b[tid];
#pragma unroll 8
        for (int h = 0; h < H_; ++h)
            s += hs[h] * W2w[h * U_ + tid];
        g_bias[bid * U_ + tid] = s + W1b[tid];
    } else if (bid < 192) {
        __shared__ float t[32][33];
        const int tb = bid - 64;
        const int u0 = (tb & 15) * 32, e0 = (tb >> 4) * 32;
        const int tx = tid & 31, ty = tid >> 5;   // ty 0..15
        t[ty][tx]      = W1w[(e0 + ty) * U_ + u0 + tx];
        t[ty + 16][tx] = W1w[(e0 + ty + 16) * U_ + u0 + tx];
        __syncthreads();
        g_W1Th[(u0 + ty) * E_ + e0 + tx]      = __float2half_rn(t[tx][ty]);
        g_W1Th[(u0 + ty + 16) * E_ + e0 + tx] = __float2half_rn(t[tx][ty + 16]);
    } else {
        ctx[(bid - 192) * 512 + tid] = 0.f;   // 32 * 512 = 16384 = B_*E_
    }
}

// ---------------------------------------------------------------------------
// K2: fused fp16 MMA GEMM (fp16 acc) + tanh(f16x2) + dot(V) -> scores
// CTA: 256 thr = 8 warps in 2(m) x 4(n); warp tile 64x64; CTA tile 128 x 256.
// Unified 16-slice pipeline (u-half x k32), ONE __syncthreads per slice.
// A (128x256) resident fp16; B cp.async double-buffer. 2 CTAs/SM.
// ---------------------------------------------------------------------------
__device__ __forceinline__ void epilogue_half(
    uint32_t acc[4][8][2], const __half2* biasH, const __half2* vwH, float* sred,
    int wm, int wn, int q, int t4)
{
#pragma unroll
    for (int mt = 0; mt < 4; ++mt) {
        float p0 = 0.f, p1 = 0.f;
#pragma unroll
        for (int nt = 0; nt < 8; ++nt) {
            const int cp = (wn + nt * 8 + t4 * 2) >> 1;   // half2 pair index
            const __half2 bb = biasH[cp];
            const __half2 vv = vwH[cp];
            __half2 s0 = __hadd2(*(__half2*)&acc[mt][nt][0], bb);
            __half2 s1 = __hadd2(*(__half2*)&acc[mt][nt][1], bb);
            __half2 m0 = __hmul2(tanh_h2(s0), vv);
            __half2 m1 = __hmul2(tanh_h2(s1), vv);
            float2 f0 = __half22float2(m0);
            float2 f1 = __half22float2(m1);
            p0 += f0.x + f0.y;
            p1 += f1.x + f1.y;
        }
        p0 += __shfl_xor_sync(0xffffffffu, p0, 1);
        p0 += __shfl_xor_sync(0xffffffffu, p0, 2);
        p1 += __shfl_xor_sync(0xffffffffu, p1, 1);
        p1 += __shfl_xor_sync(0xffffffffu, p1, 2);
        if (t4 == 0) {
            atomicAdd(&sred[wm + mt * 16 + q], p0);
            atomicAdd(&sred[wm + mt * 16 + q + 8], p1);
        }
    }
}

__global__ __launch_bounds__(256, 2) void fused_score_mma(
    const float* __restrict__ features, const float* __restrict__ Vw)
{
    extern __shared__ char smem[];
    const uint32_t sb = smem_u32(smem);

    const int tid  = threadIdx.x;
    const int lane = tid & 31;
    const int warp = tid >> 5;
    const int q    = lane >> 2;          // 0..7
    const int t4   = lane & 3;           // 0..3
    const int wm   = (warp & 1) * 64;    // 0 / 64
    const int wn   = (warp >> 1) * 64;   // 0..192
    const int r0   = blockIdx.x * 128;   // flattened (b,f) row base
    const int b    = r0 >> 12;

    __half2* biasH = (__half2*)(smem + OFF_BIAS);   // 256 pairs (both halves)
    __half2* vwH   = (__half2*)(smem + OFF_VW);
    float*   sred  = (float*)(smem + OFF_SRED);

    // B cp.async mapping: per thread 4 chunks; 16B part fixed, rows strided 64
    const int bpart = tid & 3;            // 16B chunk within 64B row payload
    const int brow0 = tid >> 2;           // first row (0..63)

    // issue prefetch for slice 0 FIRST (latency hides behind A staging)
#pragma unroll
    for (int j = 0; j < 4; ++j) {
        int row = brow0 + j * 64;         // u-row within current half (uh=0)
        CP_ASYNC_16(sb + OFF_BS + row * LDB_BYTES + bpart * 16,
                    (const char*)(g_W1Th + (size_t)row * E_ + bpart * 8));
    }
    CP_COMMIT();

    // ---- prologue: bias/V both halves (packed half2), zero sred, stage A --
    {
        const float2 bb = ((const float2*)(g_bias + b * U_))[tid];
        const float2 vv = ((const float2*)Vw)[tid];
        biasH[tid] = __floats2half2_rn(bb.x, bb.y);
        vwH[tid]   = __floats2half2_rn(vv.x, vv.y);
        if (tid < 128) sred[tid] = 0.f;

        const int row = tid >> 1;
        const int kh  = (tid & 1) * 128;
        const float4* src =
            (const float4*)(features + (size_t)(r0 + row) * E_ + kh);
        char* dst = smem + OFF_AS + row * (LDA * 2) + kh * 2;
#pragma unroll 8
        for (int j = 0; j < 32; ++j) {
            float4 v = src[j];
            __half2 h0 = __floats2half2_rn(v.x, v.y);
            __half2 h1 = __floats2half2_rn(v.z, v.w);
            uint2 pk = make_uint2(*(uint32_t*)&h0, *(uint32_t*)&h1);
            *(uint2*)(dst + j * 8) = pk;
        }
    }

    // per-thread ldmatrix addresses (A: 4 m-tiles of 16 rows)
    uint32_t aAddr[4];
#pragma unroll
    for (int mt = 0; mt < 4; ++mt)
        aAddr[mt] = sb + OFF_AS + (wm + mt * 16 + (lane & 15)) * (LDA * 2)
                       + ((lane >> 4) * 8) * 2;
    const uint32_t bRel =
        (wn + ((lane >> 4) & 1) * 8 + (lane & 7)) * LDB_BYTES
        + ((lane >> 3) & 1) * 16;

    uint32_t acc[4][8][2];
#pragma unroll
    for (int mt = 0; mt < 4; ++mt)
#pragma unroll
        for (int nt = 0; nt < 8; ++nt)
            acc[mt][nt][0] = acc[mt][nt][1] = 0u;

    // ---- unified 16-slice pipeline: g = uh*8 + ks, ONE barrier per slice ---
#pragma unroll 2
    for (int g = 0; g < 16; ++g) {
        const int s = g & 1;
        CP_WAIT(0);               // slice g landed (committed at g-1)
        __syncthreads();          // visible to all; stage 1-s free to overwrite

        if (g < 15) {
            const int gn  = g + 1;
            const int u0n = (gn >> 3) << 8;     // next half base
            const int kn  = (gn & 7) * 32;      // next k offset (halves)
            const uint32_t d2 = sb + OFF_BS + (1 - s) * BSTG;
#pragma unroll
            for (int j = 0; j < 4; ++j) {
                int row = brow0 + j * 64;
                CP_ASYNC_16(d2 + row * LDB_BYTES + bpart * 16,
                            (const char*)(g_W1Th + (size_t)(u0n + row) * E_
                                          + kn + bpart * 8));
            }
            CP_COMMIT();
        }

        const uint32_t bA = sb + OFF_BS + s * BSTG + bRel;
#pragma unroll
        for (int kk = 0; kk < 2; ++kk) {
            const int kg = (g & 7) * 32 + kk * 16;   // abs k (halves) in As
            uint32_t a[4][4];
#pragma unroll
            for (int mt = 0; mt < 4; ++mt)
                LDM_X4(a[mt][0], a[mt][1], a[mt][2], a[mt][3],
                       aAddr[mt] + kg * 2);
#pragma unroll
            for (int ntp = 0; ntp < 4; ++ntp) {
                uint32_t b0, b1, b2, b3;
                LDM_X4(b0, b1, b2, b3,
                       bA + ntp * (16 * LDB_BYTES) + kk * 32);
#pragma unroll
                for (int mt = 0; mt < 4; ++mt) {
                    mma_f16acc(acc[mt][2 * ntp],     a[mt], b0, b1);
                    mma_f16acc(acc[mt][2 * ntp + 1], a[mt], b2, b3);
                }
            }
        }

        if (g == 7) {   // first U-half complete: fold into sred, reset acc
            epilogue_half(acc, biasH, vwH, sred, wm, wn, q, t4);
#pragma unroll
            for (int mt = 0; mt < 4; ++mt)
#pragma unroll
                for (int nt = 0; nt < 8; ++nt)
                    acc[mt][nt][0] = acc[mt][nt][1] = 0u;
        }
    }

    // second U-half epilogue
    epilogue_half(acc, biasH + 128, vwH + 128, sred, wm, wn, q, t4);

    __syncthreads();
    if (tid < 128) g_scores[r0 + tid] = sred[tid];
}

// ---------------------------------------------------------------------------
// K3: softmax over F per batch
// ---------------------------------------------------------------------------
__global__ __launch_bounds__(256) void softmax_kernel(float* __restrict__ out_w)
{
    const int b = blockIdx.x, tid = threadIdx.x;
    const float* s = g_scores + b * F_;
    float loc[16];
    float m = -1e30f;
#pragma unroll
    for (int i = 0; i < 16; ++i) {
        loc[i] = s[i * 256 + tid];
        m = fmaxf(m, loc[i]);
    }
    __shared__ float redm[8], reds[8];
#pragma unroll
    for (int o = 16; o > 0; o >>= 1) m = fmaxf(m, __shfl_xor_sync(0xffffffffu, m, o));
    if ((tid & 31) == 0) redm[tid >> 5] = m;
    __syncthreads();
    m = redm[0];
#pragma unroll
    for (int i = 1; i < 8; ++i) m = fmaxf(m, redm[i]);

    float sum = 0.f;
#pragma unroll
    for (int i = 0; i < 16; ++i) {
        loc[i] = __expf(loc[i] - m);
        sum += loc[i];
    }
#pragma unroll
    for (int o = 16; o > 0; o >>= 1) sum += __shfl_xor_sync(0xffffffffu, sum, o);
    if ((tid & 31) == 0) reds[tid >> 5] = sum;
    __syncthreads();
    sum = 0.f;
#pragma unroll
    for (int i = 0; i < 8; ++i) sum += reds[i];
    float inv = 1.f / sum;
#pragma unroll
    for (int i = 0; i < 16; ++i)
        out_w[b * F_ + i * 256 + tid] = loc[i] * inv;
}

// ---------------------------------------------------------------------------
// K4: context[b][e] = sum_f w[b][f] * features[b][f][e]
// ---------------------------------------------------------------------------
__global__ __launch_bounds__(256) void context_kernel(
    const float* __restrict__ features, const float* __restrict__ w,
    float* __restrict__ ctx)
{
    __shared__ float ws[256];
    const int b = blockIdx.y;
    const int f0 = blockIdx.x * 256;
    const int tid = threadIdx.x;
    ws[tid] = w[b * F_ + f0 + tid];
    __syncthreads();
    const float* fp = features + (long long)(b * F_ + f0) * E_ + tid;
    float acc0 = 0.f, acc1 = 0.f;
#pragma unroll 8
    for (int i = 0; i < 256; i += 2) {
        acc0 += ws[i]     * fp[(long long)i * E_];
        acc1 += ws[i + 1] * fp[(long long)(i + 1) * E_];
    }
    atomicAdd(&ctx[b * E_ + tid], acc0 + acc1);
}

// ---------------------------------------------------------------------------
extern "C" void kernel_launch(void* const* d_in, const int* in_sizes, int n_in,
                              void* d_out, int out_size)
{
    const float* features = (const float*)d_in[0];
    const float* hidden   = (const float*)d_in[1];
    const float* W1w      = (const float*)d_in[2];
    const float* W1b      = (const float*)d_in[3];
    const float* W2w      = (const float*)d_in[4];
    const float* W2b      = (const float*)d_in[5];
    const float* Vw       = (const float*)d_in[6];
    // d_in[7] = V_b: constant shift of scores -> cancels in softmax; scores not output.

    float* out  = (float*)d_out;
    float* ctx  = out;              // (64, 256)
    float* wout = out + B_ * E_;    // (64, 4096, 1)

    prep_kernel<<<224, 512>>>(hidden, W2w, W2b, W1b, W1w, ctx);

    cudaFuncSetAttribute(fused_score_mma,
                         cudaFuncAttributeMaxDynamicSharedMemorySize, SMEM_K2);
    fused_score_mma<<<(B_ * F_) / 128, 256, SMEM_K2>>>(features, Vw);

    softmax_kernel<<<B_, 256>>>(wout);
    context_kernel<<<dim3(F_ / 256, B_), 256>>>(features, wout, ctx);
}

// round 12
// speedup vs baseline: 1.4371x; 1.4371x over previous
#include <cuda_runtime.h>
#include <cuda_fp16.h>
#include <cstdint>

#define B_ 64
#define F_ 4096
#define E_ 256
#define H_ 512
#define U_ 512

// ---------------- scratch (__device__ globals: allocation-free rule) -------
__device__ float  g_bias[B_ * U_];     // W1_b[u] + W2_b[u] + hidden@W2
__device__ float  g_scores[B_ * F_];   // pre-softmax scores (V_b dropped: softmax-invariant)
__device__ __half g_W1Th[U_ * E_];     // W1 transposed (u-major, e contiguous) as fp16

__device__ __forceinline__ float tanh_fast(float x) {
    float y; asm("tanh.approx.f32 %0, %1;" : "=f"(y) : "f"(x)); return y;
}
__device__ __forceinline__ uint32_t smem_u32(const void* p) {
    uint32_t a;
    asm("{ .reg .u64 t; cvta.to.shared.u64 t, %1; cvt.u32.u64 %0, t; }" : "=r"(a) : "l"(p));
    return a;
}

#define LDM_X4(r0, r1, r2, r3, addr) \
    asm volatile("ldmatrix.sync.aligned.m8n8.x4.shared.b16 {%0,%1,%2,%3}, [%4];" \
        : "=r"(r0), "=r"(r1), "=r"(r2), "=r"(r3) : "r"(addr))

#define CP_ASYNC_16(dst, src) \
    asm volatile("cp.async.cg.shared.global [%0], [%1], 16;" :: "r"(dst), "l"(src))
#define CP_COMMIT() asm volatile("cp.async.commit_group;" ::: "memory")
#define CP_WAIT(n)  asm volatile("cp.async.wait_group %0;" :: "n"(n) : "memory")

// fp16-accumulate MMA: D,C = 2 regs (4 halves)
__device__ __forceinline__ void mma_f16acc(uint32_t* c, const uint32_t* a,
                                           uint32_t b0, uint32_t b1) {
    asm volatile(
        "mma.sync.aligned.m16n8k16.row.col.f16.f16.f16.f16 "
        "{%0,%1}, {%2,%3,%4,%5}, {%6,%7}, {%0,%1};"
        : "+r"(c[0]), "+r"(c[1])
        : "r"(a[0]), "r"(a[1]), "r"(a[2]), "r"(a[3]), "r"(b0), "r"(b1));
}

// ---------------- smem layout for K2 (byte offsets) ------------------------
// CTA tile: 128 rows (A resident) x 512 u (16 k32-slices); 2 CTAs/SM.
#define LDA 264                 // halves per A row (256+8 pad) -> 528B, conflict-free
#define LDB_BYTES 80            // B row: 32 halves (64B) + 16B pad -> conflict-free ldsm
#define BSTG 20480              // 256 rows * 80B per B stage
#define OFF_AS   0              // 128 * 528 = 67584
#define OFF_BS   67584          // 2 stages * 20480 = 40960 -> 108544
#define OFF_BIAS 108544         // 512 floats (both U-halves) -> 110592
#define OFF_VW   110592         // 512 floats -> 112640
#define OFF_SRED 112640         // 128 floats -> 113152
#define SMEM_K2  113152         // x2 CTAs = 226304 B <= 228KB budget

// ---------------------------------------------------------------------------
// K1: merged prep — blocks [0,64): bias; [64,192): W1 transpose; [192,224): zero ctx
// ---------------------------------------------------------------------------
__global__ __launch_bounds__(512) void prep_kernel(
    const float* __restrict__ hidden, const float* __restrict__ W2w,
    const float* __restrict__ W2b, const float* __restrict__ W1b,
    const float* __restrict__ W1w, float* __restrict__ ctx)
{
    const int bid = blockIdx.x;
    const int tid = threadIdx.x;
    if (bid < 64) {
        __shared__ float hs[H_];
        hs[tid] = hidden[bid * H_ + tid];
        __syncthreads();
        float s = W2b[tid];
#pragma unroll 8
        for (int h = 0; h < H_; ++h)
            s += hs[h] * W2w[h * U_ + tid];
        g_bias[bid * U_ + tid] = s + W1b[tid];
    } else if (bid < 192) {
        __shared__ float t[32][33];
        const int tb = bid - 64;
        const int u0 = (tb & 15) * 32, e0 = (tb >> 4) * 32;
        const int tx = tid & 31, ty = tid >> 5;   // ty 0..15
        t[ty][tx]      = W1w[(e0 + ty) * U_ + u0 + tx];
        t[ty + 16][tx] = W1w[(e0 + ty + 16) * U_ + u0 + tx];
        __syncthreads();
        g_W1Th[(u0 + ty) * E_ + e0 + tx]      = __float2half_rn(t[tx][ty]);
        g_W1Th[(u0 + ty + 16) * E_ + e0 + tx] = __float2half_rn(t[tx][ty + 16]);
    } else {
        ctx[(bid - 192) * 512 + tid] = 0.f;   // 32 * 512 = 16384 = B_*E_
    }
}

// ---------------------------------------------------------------------------
// K2: fused fp16 MMA GEMM (fp16 acc) + tanh + dot(V) -> scores
// (round-10 proven version, f32 epilogue)
// CTA: 256 thr = 8 warps in 2(m) x 4(n); warp tile 64x64; CTA tile 128 x 256.
// Unified 16-slice pipeline (u-half x k32), ONE __syncthreads per slice.
// A (128x256) resident fp16; B cp.async double-buffer. 2 CTAs/SM.
// ---------------------------------------------------------------------------
__device__ __forceinline__ void epilogue_half(
    uint32_t acc[4][8][2], const float* biasS, const float* vwS, float* sred,
    int wm, int wn, int q, int t4)
{
#pragma unroll
    for (int mt = 0; mt < 4; ++mt) {
        float p0 = 0.f, p1 = 0.f;
#pragma unroll
        for (int nt = 0; nt < 8; ++nt) {
            const int c = wn + nt * 8 + t4 * 2;
            const float bb0 = biasS[c], bb1 = biasS[c + 1];
            const float v0 = vwS[c],   v1 = vwS[c + 1];
            float2 f0 = __half22float2(*(__half2*)&acc[mt][nt][0]);
            float2 f1 = __half22float2(*(__half2*)&acc[mt][nt][1]);
            p0 += tanh_fast(f0.x + bb0) * v0 + tanh_fast(f0.y + bb1) * v1;
            p1 += tanh_fast(f1.x + bb0) * v0 + tanh_fast(f1.y + bb1) * v1;
        }
        p0 += __shfl_xor_sync(0xffffffffu, p0, 1);
        p0 += __shfl_xor_sync(0xffffffffu, p0, 2);
        p1 += __shfl_xor_sync(0xffffffffu, p1, 1);
        p1 += __shfl_xor_sync(0xffffffffu, p1, 2);
        if (t4 == 0) {
            atomicAdd(&sred[wm + mt * 16 + q], p0);
            atomicAdd(&sred[wm + mt * 16 + q + 8], p1);
        }
    }
}

__global__ __launch_bounds__(256, 2) void fused_score_mma(
    const float* __restrict__ features, const float* __restrict__ Vw)
{
    extern __shared__ char smem[];
    const uint32_t sb = smem_u32(smem);

    const int tid  = threadIdx.x;
    const int lane = tid & 31;
    const int warp = tid >> 5;
    const int q    = lane >> 2;          // 0..7
    const int t4   = lane & 3;           // 0..3
    const int wm   = (warp & 1) * 64;    // 0 / 64
    const int wn   = (warp >> 1) * 64;   // 0..192
    const int r0   = blockIdx.x * 128;   // flattened (b,f) row base
    const int b    = r0 >> 12;

    float* biasS = (float*)(smem + OFF_BIAS);
    float* vwS   = (float*)(smem + OFF_VW);
    float* sred  = (float*)(smem + OFF_SRED);

    // B cp.async mapping: per thread 4 chunks; 16B part fixed, rows strided 64
    const int bpart = tid & 3;            // 16B chunk within 64B row payload
    const int brow0 = tid >> 2;           // first row (0..63)

    // issue prefetch for slice 0 FIRST (latency hides behind A staging)
#pragma unroll
    for (int j = 0; j < 4; ++j) {
        int row = brow0 + j * 64;         // u-row within current half (uh=0)
        CP_ASYNC_16(sb + OFF_BS + row * LDB_BYTES + bpart * 16,
                    (const char*)(g_W1Th + (size_t)row * E_ + bpart * 8));
    }
    CP_COMMIT();

    // ---- prologue: bias/V both halves, zero sred, stage A resident --------
    {
        biasS[tid]       = g_bias[b * U_ + tid];
        biasS[tid + 256] = g_bias[b * U_ + tid + 256];
        vwS[tid]         = Vw[tid];
        vwS[tid + 256]   = Vw[tid + 256];
        if (tid < 128) sred[tid] = 0.f;

        const int row = tid >> 1;
        const int kh  = (tid & 1) * 128;
        const float4* src =
            (const float4*)(features + (size_t)(r0 + row) * E_ + kh);
        char* dst = smem + OFF_AS + row * (LDA * 2) + kh * 2;
#pragma unroll 8
        for (int j = 0; j < 32; ++j) {
            float4 v = src[j];
            __half2 h0 = __floats2half2_rn(v.x, v.y);
            __half2 h1 = __floats2half2_rn(v.z, v.w);
            uint2 pk = make_uint2(*(uint32_t*)&h0, *(uint32_t*)&h1);
            *(uint2*)(dst + j * 8) = pk;
        }
    }

    // per-thread ldmatrix addresses (A: 4 m-tiles of 16 rows)
    uint32_t aAddr[4];
#pragma unroll
    for (int mt = 0; mt < 4; ++mt)
        aAddr[mt] = sb + OFF_AS + (wm + mt * 16 + (lane & 15)) * (LDA * 2)
                       + ((lane >> 4) * 8) * 2;
    const uint32_t bRel =
        (wn + ((lane >> 4) & 1) * 8 + (lane & 7)) * LDB_BYTES
        + ((lane >> 3) & 1) * 16;

    uint32_t acc[4][8][2];
#pragma unroll
    for (int mt = 0; mt < 4; ++mt)
#pragma unroll
        for (int nt = 0; nt < 8; ++nt)
            acc[mt][nt][0] = acc[mt][nt][1] = 0u;

    // ---- unified 16-slice pipeline: g = uh*8 + ks, ONE barrier per slice ---
#pragma unroll 2
    for (int g = 0; g < 16; ++g) {
        const int s = g & 1;
        CP_WAIT(0);               // slice g landed (committed at g-1)
        __syncthreads();          // visible to all; stage 1-s free to overwrite

        if (g < 15) {
            const int gn  = g + 1;
            const int u0n = (gn >> 3) << 8;     // next half base
            const int kn  = (gn & 7) * 32;      // next k offset (halves)
            const uint32_t d2 = sb + OFF_BS + (1 - s) * BSTG;
#pragma unroll
            for (int j = 0; j < 4; ++j) {
                int row = brow0 + j * 64;
                CP_ASYNC_16(d2 + row * LDB_BYTES + bpart * 16,
                            (const char*)(g_W1Th + (size_t)(u0n + row) * E_
                                          + kn + bpart * 8));
            }
            CP_COMMIT();
        }

        const uint32_t bA = sb + OFF_BS + s * BSTG + bRel;
#pragma unroll
        for (int kk = 0; kk < 2; ++kk) {
            const int kg = (g & 7) * 32 + kk * 16;   // abs k (halves) in As
            uint32_t a[4][4];
#pragma unroll
            for (int mt = 0; mt < 4; ++mt)
                LDM_X4(a[mt][0], a[mt][1], a[mt][2], a[mt][3],
                       aAddr[mt] + kg * 2);
#pragma unroll
            for (int ntp = 0; ntp < 4; ++ntp) {
                uint32_t b0, b1, b2, b3;
                LDM_X4(b0, b1, b2, b3,
                       bA + ntp * (16 * LDB_BYTES) + kk * 32);
#pragma unroll
                for (int mt = 0; mt < 4; ++mt) {
                    mma_f16acc(acc[mt][2 * ntp],     a[mt], b0, b1);
                    mma_f16acc(acc[mt][2 * ntp + 1], a[mt], b2, b3);
                }
            }
        }

        if (g == 7) {   // first U-half complete: fold into sred, reset acc
            epilogue_half(acc, biasS, vwS, sred, wm, wn, q, t4);
#pragma unroll
            for (int mt = 0; mt < 4; ++mt)
#pragma unroll
                for (int nt = 0; nt < 8; ++nt)
                    acc[mt][nt][0] = acc[mt][nt][1] = 0u;
        }
    }

    // second U-half epilogue
    epilogue_half(acc, biasS + 256, vwS + 256, sred, wm, wn, q, t4);

    __syncthreads();
    if (tid < 128) g_scores[r0 + tid] = sred[tid];
}

// ---------------------------------------------------------------------------
// K3: softmax over F per batch
// ---------------------------------------------------------------------------
__global__ __launch_bounds__(256) void softmax_kernel(float* __restrict__ out_w)
{
    const int b = blockIdx.x, tid = threadIdx.x;
    const float* s = g_scores + b * F_;
    float loc[16];
    float m = -1e30f;
#pragma unroll
    for (int i = 0; i < 16; ++i) {
        loc[i] = s[i * 256 + tid];
        m = fmaxf(m, loc[i]);
    }
    __shared__ float redm[8], reds[8];
#pragma unroll
    for (int o = 16; o > 0; o >>= 1) m = fmaxf(m, __shfl_xor_sync(0xffffffffu, m, o));
    if ((tid & 31) == 0) redm[tid >> 5] = m;
    __syncthreads();
    m = redm[0];
#pragma unroll
    for (int i = 1; i < 8; ++i) m = fmaxf(m, redm[i]);

    float sum = 0.f;
#pragma unroll
    for (int i = 0; i < 16; ++i) {
        loc[i] = __expf(loc[i] - m);
        sum += loc[i];
    }
#pragma unroll
    for (int o = 16; o > 0; o >>= 1) sum += __shfl_xor_sync(0xffffffffu, sum, o);
    if ((tid & 31) == 0) reds[tid >> 5] = sum;
    __syncthreads();
    sum = 0.f;
#pragma unroll
    for (int i = 0; i < 8; ++i) sum += reds[i];
    float inv = 1.f / sum;
#pragma unroll
    for (int i = 0; i < 16; ++i)
        out_w[b * F_ + i * 256 + tid] = loc[i] * inv;
}

// ---------------------------------------------------------------------------
// K4: context[b][e] = sum_f w[b][f] * features[b][f][e]
// 4 independent accumulators -> deeper LDG batching (MLP), same traffic.
// ---------------------------------------------------------------------------
__global__ __launch_bounds__(256) void context_kernel(
    const float* __restrict__ features, const float* __restrict__ w,
    float* __restrict__ ctx)
{
    __shared__ float ws[256];
    const int b = blockIdx.y;
    const int f0 = blockIdx.x * 256;
    const int tid = threadIdx.x;
    ws[tid] = w[b * F_ + f0 + tid];
    __syncthreads();
    const float* fp = features + (long long)(b * F_ + f0) * E_ + tid;
    float a0 = 0.f, a1 = 0.f, a2 = 0.f, a3 = 0.f;
#pragma unroll 4
    for (int i = 0; i < 256; i += 4) {
        a0 += ws[i]     * fp[(long long)i * E_];
        a1 += ws[i + 1] * fp[(long long)(i + 1) * E_];
        a2 += ws[i + 2] * fp[(long long)(i + 2) * E_];
        a3 += ws[i + 3] * fp[(long long)(i + 3) * E_];
    }
    atomicAdd(&ctx[b * E_ + tid], (a0 + a1) + (a2 + a3));
}

// ---------------------------------------------------------------------------
extern "C" void kernel_launch(void* const* d_in, const int* in_sizes, int n_in,
                              void* d_out, int out_size)
{
    const float* features = (const float*)d_in[0];
    const float* hidden   = (const float*)d_in[1];
    const float* W1w      = (const float*)d_in[2];
    const float* W1b      = (const float*)d_in[3];
    const float* W2w      = (const float*)d_in[4];
    const float* W2b      = (const float*)d_in[5];
    const float* Vw       = (const float*)d_in[6];
    // d_in[7] = V_b: constant shift of scores -> cancels in softmax; scores not output.

    float* out  = (float*)d_out;
    float* ctx  = out;              // (64, 256)
    float* wout = out + B_ * E_;    // (64, 4096, 1)

    prep_kernel<<<224, 512>>>(hidden, W2w, W2b, W1b, W1w, ctx);

    cudaFuncSetAttribute(fused_score_mma,
                         cudaFuncAttributeMaxDynamicSharedMemorySize, SMEM_K2);
    fused_score_mma<<<(B_ * F_) / 128, 256, SMEM_K2>>>(features, Vw);

    softmax_kernel<<<B_, 256>>>(wout);
    context_kernel<<<dim3(F_ / 256, B_), 256>>>(features, wout, ctx);
}